// round 2
// baseline (speedup 1.0000x reference)
#include <cuda_runtime.h>
#include <math.h>

#define TT 4096
#define HH 2048
#define NH 16
#define NKV 8
#define HD 128
#define QS 2048
#define KVS 1024
#define QKVN 4096   // QS + 2*KVS

// ---------------- scratch (device globals; no allocation allowed) ----------
__device__ float g_qkv[(size_t)TT * QKVN];   // 64 MB : qkv projection output
__device__ float g_q[(size_t)TT * QS];       // 32 MB : normed+roped Q
__device__ float g_k[(size_t)TT * KVS];      // 16 MB : normed+roped K
__device__ float g_att[(size_t)TT * QS];     // 32 MB : attention output

// ---------------- generic fp32 tiled GEMM: C[M,N] = A[M,K] @ B[K,N] --------
// BM=BN=64, BK=16, 256 threads, 4x4 fragment per thread.
__global__ void gemm64(const float* __restrict__ A, const float* __restrict__ B,
                       float* __restrict__ C, int M, int N, int K) {
    __shared__ float As[16][65];   // transposed: As[k][m]
    __shared__ float Bs[16][64];   // Bs[k][n]

    int tid = threadIdx.x;
    int tx = tid & 15;         // col group
    int ty = tid >> 4;         // row group
    int m0 = blockIdx.y * 64;
    int n0 = blockIdx.x * 64;

    int arow = tid >> 2, akq = tid & 3;     // A load: 64 rows x 4 float4
    int brow = tid >> 4, bcq = tid & 15;    // B load: 16 rows x 16 float4

    float acc[4][4];
#pragma unroll
    for (int i = 0; i < 4; i++)
#pragma unroll
        for (int j = 0; j < 4; j++) acc[i][j] = 0.f;

    for (int k0 = 0; k0 < K; k0 += 16) {
        float4 av = *(const float4*)&A[(size_t)(m0 + arow) * K + k0 + 4 * akq];
        float4 bv = *(const float4*)&B[(size_t)(k0 + brow) * N + n0 + 4 * bcq];
        As[4 * akq + 0][arow] = av.x;
        As[4 * akq + 1][arow] = av.y;
        As[4 * akq + 2][arow] = av.z;
        As[4 * akq + 3][arow] = av.w;
        *(float4*)&Bs[brow][4 * bcq] = bv;
        __syncthreads();
#pragma unroll
        for (int k = 0; k < 16; k++) {
            float a[4], b[4];
#pragma unroll
            for (int i = 0; i < 4; i++) a[i] = As[k][ty * 4 + i];
#pragma unroll
            for (int j = 0; j < 4; j++) b[j] = Bs[k][tx * 4 + j];
#pragma unroll
            for (int i = 0; i < 4; i++)
#pragma unroll
                for (int j = 0; j < 4; j++) acc[i][j] = fmaf(a[i], b[j], acc[i][j]);
        }
        __syncthreads();
    }
#pragma unroll
    for (int i = 0; i < 4; i++) {
        float4 v = make_float4(acc[i][0], acc[i][1], acc[i][2], acc[i][3]);
        *(float4*)&C[(size_t)(m0 + ty * 4 + i) * N + n0 + tx * 4] = v;
    }
}

// ---------------- per-head RMSNorm + RoPE (one warp per (token, head)) -----
__global__ void normrope(const int* __restrict__ pos,
                         const float* __restrict__ qw,
                         const float* __restrict__ kw) {
    int gw = (blockIdx.x * blockDim.x + threadIdx.x) >> 5;
    int lane = threadIdx.x & 31;
    if (gw >= TT * (NH + NKV)) return;
    int t = gw / (NH + NKV);
    int hh = gw - t * (NH + NKV);

    const float* src;
    float* dst;
    const float* w;
    if (hh < NH) {
        src = g_qkv + (size_t)t * QKVN + hh * HD;
        dst = g_q + (size_t)t * QS + hh * HD;
        w = qw;
    } else {
        int kk = hh - NH;
        src = g_qkv + (size_t)t * QKVN + QS + kk * HD;
        dst = g_k + (size_t)t * KVS + kk * HD;
        w = kw;
    }
    float v0 = src[lane], v1 = src[lane + 32], v2 = src[lane + 64], v3 = src[lane + 96];
    float ss = v0 * v0 + v1 * v1 + v2 * v2 + v3 * v3;
#pragma unroll
    for (int o = 16; o; o >>= 1) ss += __shfl_xor_sync(0xffffffffu, ss, o);
    float inv = rsqrtf(ss * (1.0f / 128.0f) + 1e-6f);
    v0 *= inv * w[lane];
    v1 *= inv * w[lane + 32];
    v2 *= inv * w[lane + 64];
    v3 *= inv * w[lane + 96];

    // RoPE (neox rotate-half): pairs (lane, lane+64) and (lane+32, lane+96)
    float p = (float)pos[t];
    const float LOG2_THETA = 19.931568569324174f;  // log2(1e6)
    float f0 = (float)lane;
    float f1 = (float)(lane + 32);
    float if0 = exp2f(-LOG2_THETA * (2.0f * f0) * (1.0f / 128.0f));
    float if1 = exp2f(-LOG2_THETA * (2.0f * f1) * (1.0f / 128.0f));
    float s0, c0, s1, c1;
    sincosf(p * if0, &s0, &c0);
    sincosf(p * if1, &s1, &c1);
    dst[lane]      = v0 * c0 - v2 * s0;
    dst[lane + 64] = v2 * c0 + v0 * s0;
    dst[lane + 32] = v1 * c1 - v3 * s1;
    dst[lane + 96] = v3 * c1 + v1 * s1;
}

// ---------------- causal GQA flash attention (fp32) ------------------------
// Block: 256 threads, BM=64 query rows, BN=64 key cols, HD=128.
#define FL_SMEM_FLOATS (128 * 65 + 128 * 65 + 64 * 65 + 64 * 3)
#define FL_SMEM_BYTES (FL_SMEM_FLOATS * 4)

__global__ void flash_kernel() {
    extern __shared__ float sm[];
    float* Qs = sm;                    // [128][65]   transposed Q tile (pre-scaled)
    float* KVs = Qs + 128 * 65;        // K: [128][65] transposed; then V: [64][128]
    float* Ss = KVs + 128 * 65;        // [64][65]   S^T: Ss[c*65 + r]
    float* m_s = Ss + 64 * 65;
    float* l_s = m_s + 64;
    float* al_s = l_s + 64;

    int tid = threadIdx.x;
    int tx = tid & 15;        // col group (S: 4 cols, O: 8 cols)
    int ty = tid >> 4;        // row group (4 rows)
    int qt = gridDim.x - 1 - blockIdx.x;   // heavy tiles launch first
    int h = blockIdx.y;
    int kv = h >> 1;
    int q0 = qt * 64;
    const float scale = 0.08838834764831845f;  // 128^-0.5

    // load Q tile, transposed + pre-scaled
    for (int idx = tid; idx < 64 * 32; idx += 256) {
        int r = idx >> 5, dq = idx & 31;
        float4 v = *(const float4*)&g_q[(size_t)(q0 + r) * QS + h * HD + 4 * dq];
        Qs[(4 * dq + 0) * 65 + r] = v.x * scale;
        Qs[(4 * dq + 1) * 65 + r] = v.y * scale;
        Qs[(4 * dq + 2) * 65 + r] = v.z * scale;
        Qs[(4 * dq + 3) * 65 + r] = v.w * scale;
    }
    if (tid < 64) {
        m_s[tid] = -INFINITY;
        l_s[tid] = 0.f;
    }
    float o[4][8];
#pragma unroll
    for (int i = 0; i < 4; i++)
#pragma unroll
        for (int j = 0; j < 8; j++) o[i][j] = 0.f;
    __syncthreads();

    for (int kt = 0; kt <= qt; kt++) {
        int k0 = kt * 64;
        // load K tile transposed
        for (int idx = tid; idx < 64 * 32; idx += 256) {
            int r = idx >> 5, dq = idx & 31;
            float4 v = *(const float4*)&g_k[(size_t)(k0 + r) * KVS + kv * HD + 4 * dq];
            KVs[(4 * dq + 0) * 65 + r] = v.x;
            KVs[(4 * dq + 1) * 65 + r] = v.y;
            KVs[(4 * dq + 2) * 65 + r] = v.z;
            KVs[(4 * dq + 3) * 65 + r] = v.w;
        }
        __syncthreads();

        // S = (Q*scale) K^T
        float acc[4][4];
#pragma unroll
        for (int i = 0; i < 4; i++)
#pragma unroll
            for (int j = 0; j < 4; j++) acc[i][j] = 0.f;
#pragma unroll 4
        for (int k = 0; k < 128; k++) {
            float a[4], b[4];
#pragma unroll
            for (int i = 0; i < 4; i++) a[i] = Qs[k * 65 + ty * 4 + i];
#pragma unroll
            for (int j = 0; j < 4; j++) b[j] = KVs[k * 65 + tx * 4 + j];
#pragma unroll
            for (int i = 0; i < 4; i++)
#pragma unroll
                for (int j = 0; j < 4; j++) acc[i][j] = fmaf(a[i], b[j], acc[i][j]);
        }
        if (kt == qt) {  // causal mask on the diagonal tile (k0 == q0)
#pragma unroll
            for (int i = 0; i < 4; i++)
#pragma unroll
                for (int j = 0; j < 4; j++)
                    if (tx * 4 + j > ty * 4 + i) acc[i][j] = -1e30f;
        }
#pragma unroll
        for (int i = 0; i < 4; i++)
#pragma unroll
            for (int j = 0; j < 4; j++)
                Ss[(tx * 4 + j) * 65 + (ty * 4 + i)] = acc[i][j];
        __syncthreads();

        // load V tile (row-major) into the K buffer; independent of softmax below
        for (int idx = tid; idx < 64 * 32; idx += 256) {
            int r = idx >> 5, dq = idx & 31;
            float4 v = *(const float4*)
                &g_qkv[(size_t)(k0 + r) * QKVN + (QS + KVS) + kv * HD + 4 * dq];
            *(float4*)&KVs[r * 128 + 4 * dq] = v;
        }

        // online softmax: 4 lanes per row
        {
            int row = tid >> 2, seg = tid & 3;
            float mx = -INFINITY;
#pragma unroll
            for (int jj = 0; jj < 16; jj++)
                mx = fmaxf(mx, Ss[(seg * 16 + jj) * 65 + row]);
            mx = fmaxf(mx, __shfl_xor_sync(0xffffffffu, mx, 1));
            mx = fmaxf(mx, __shfl_xor_sync(0xffffffffu, mx, 2));
            float mo = m_s[row];
            float mn = fmaxf(mo, mx);
            float alpha = __expf(mo - mn);
            float smm = 0.f;
#pragma unroll
            for (int jj = 0; jj < 16; jj++) {
                int c = seg * 16 + jj;
                float pval = __expf(Ss[c * 65 + row] - mn);
                Ss[c * 65 + row] = pval;
                smm += pval;
            }
            smm += __shfl_xor_sync(0xffffffffu, smm, 1);
            smm += __shfl_xor_sync(0xffffffffu, smm, 2);
            if (seg == 0) {
                m_s[row] = mn;
                l_s[row] = alpha * l_s[row] + smm;
                al_s[row] = alpha;
            }
        }
        __syncthreads();

        // rescale O, accumulate P @ V
        float alr[4];
#pragma unroll
        for (int i = 0; i < 4; i++) alr[i] = al_s[ty * 4 + i];
#pragma unroll
        for (int i = 0; i < 4; i++)
#pragma unroll
            for (int j = 0; j < 8; j++) o[i][j] *= alr[i];
#pragma unroll 2
        for (int kk = 0; kk < 64; kk++) {
            float pv[4];
#pragma unroll
            for (int i = 0; i < 4; i++) pv[i] = Ss[kk * 65 + ty * 4 + i];
            float4 va = *(float4*)&KVs[kk * 128 + tx * 8];
            float4 vb = *(float4*)&KVs[kk * 128 + tx * 8 + 4];
#pragma unroll
            for (int i = 0; i < 4; i++) {
                o[i][0] = fmaf(pv[i], va.x, o[i][0]);
                o[i][1] = fmaf(pv[i], va.y, o[i][1]);
                o[i][2] = fmaf(pv[i], va.z, o[i][2]);
                o[i][3] = fmaf(pv[i], va.w, o[i][3]);
                o[i][4] = fmaf(pv[i], vb.x, o[i][4]);
                o[i][5] = fmaf(pv[i], vb.y, o[i][5]);
                o[i][6] = fmaf(pv[i], vb.z, o[i][6]);
                o[i][7] = fmaf(pv[i], vb.w, o[i][7]);
            }
        }
        __syncthreads();
    }

    // epilogue
    float li[4];
#pragma unroll
    for (int i = 0; i < 4; i++) li[i] = 1.0f / l_s[ty * 4 + i];
#pragma unroll
    for (int i = 0; i < 4; i++) {
        float4 a = make_float4(o[i][0] * li[i], o[i][1] * li[i],
                               o[i][2] * li[i], o[i][3] * li[i]);
        float4 b = make_float4(o[i][4] * li[i], o[i][5] * li[i],
                               o[i][6] * li[i], o[i][7] * li[i]);
        size_t base = (size_t)(q0 + ty * 4 + i) * QS + h * HD + tx * 8;
        *(float4*)&g_att[base] = a;
        *(float4*)&g_att[base + 4] = b;
    }
}

// ---------------------------------------------------------------------------
extern "C" void kernel_launch(void* const* d_in, const int* in_sizes, int n_in,
                              void* d_out, int out_size) {
    const int* positions = (const int*)d_in[0];
    const float* hs = (const float*)d_in[1];
    const float* w_qkv = (const float*)d_in[2];
    const float* w_o = (const float*)d_in[3];
    const float* qw = (const float*)d_in[4];
    const float* kw = (const float*)d_in[5];
    float* out = (float*)d_out;

    float* p_qkv = nullptr;
    float* p_att = nullptr;
    cudaGetSymbolAddress((void**)&p_qkv, g_qkv);
    cudaGetSymbolAddress((void**)&p_att, g_att);
    cudaFuncSetAttribute(flash_kernel,
                         cudaFuncAttributeMaxDynamicSharedMemorySize, FL_SMEM_BYTES);

    // 1) QKV projection: [T,H] @ [H, QKVN]
    gemm64<<<dim3(QKVN / 64, TT / 64), 256>>>(hs, w_qkv, p_qkv, TT, QKVN, HH);
    // 2) per-head RMSNorm + RoPE
    normrope<<<(TT * (NH + NKV)) / 8, 256>>>(positions, qw, kw);
    // 3) causal GQA flash attention
    flash_kernel<<<dim3(TT / 64, NH), 256, FL_SMEM_BYTES>>>();
    // 4) output projection: [T, QS] @ [QS, H] -> d_out
    gemm64<<<dim3(HH / 64, TT / 64), 256>>>(p_att, w_o, out, TT, HH, QS);
}

// round 3
// speedup vs baseline: 5.6191x; 5.6191x over previous
#include <cuda_runtime.h>
#include <math.h>

#define TT 4096
#define HH 2048
#define NH 16
#define NKV 8
#define HD 128
#define QS 2048
#define KVS 1024
#define QKVN 4096

// ---------------- scratch (device globals; no allocation allowed) ----------
__device__ float g_qkv[(size_t)TT * QKVN];
__device__ float g_q[(size_t)TT * QS];
__device__ float g_k[(size_t)TT * KVS];
__device__ float g_att[(size_t)TT * QS];

// ---------------- tf32 helpers --------------------------------------------
__device__ __forceinline__ unsigned f2tf(float x) {
    unsigned u;
    asm("cvt.rna.tf32.f32 %0, %1;" : "=r"(u) : "f"(x));
    return u;
}

__device__ __forceinline__ void mma8(float* c, unsigned a0, unsigned a1,
                                     unsigned a2, unsigned a3,
                                     unsigned b0, unsigned b1) {
    asm volatile(
        "mma.sync.aligned.m16n8k8.row.col.f32.tf32.tf32.f32 "
        "{%0,%1,%2,%3},{%4,%5,%6,%7},{%8,%9},{%0,%1,%2,%3};"
        : "+f"(c[0]), "+f"(c[1]), "+f"(c[2]), "+f"(c[3])
        : "r"(a0), "r"(a1), "r"(a2), "r"(a3), "r"(b0), "r"(b1));
}

// ---------------- TF32 tensor-core GEMM: C[M,N] = A[M,K] @ B[K,N] ----------
// BM=128, BN=128, BK=32, 256 threads (8 warps, 2m x 4n), warp tile 64x32.
#define ASTR 36    // A smem row stride (floats): bank = (4m + k) % 32, conflict-free
#define BSTR 136   // B smem row stride: bank = (8k + n) % 32, conflict-free

__global__ __launch_bounds__(256, 1)
void gemm_tc(const float* __restrict__ A, const float* __restrict__ B,
             float* __restrict__ C, int M, int N, int K) {
    __shared__ unsigned As[128 * ASTR];
    __shared__ unsigned Bs[32 * BSTR];

    int tid = threadIdx.x;
    int w = tid >> 5, lane = tid & 31;
    int g = lane >> 2, t = lane & 3;
    int wm = (w >> 2) * 64, wn = (w & 3) * 32;
    int m0 = blockIdx.y * 128, n0 = blockIdx.x * 128;

    int am = tid >> 3, ak = (tid & 7) * 4;      // A loader: 4 rows/iter stride 32
    int bk = tid >> 5, bn = (tid & 31) * 4;     // B loader: 8 rows/iter

    float acc[4][4][4];
#pragma unroll
    for (int mt = 0; mt < 4; mt++)
#pragma unroll
        for (int nt = 0; nt < 4; nt++)
#pragma unroll
            for (int r = 0; r < 4; r++) acc[mt][nt][r] = 0.f;

    float4 ar[4], br[4];
    int nkt = K / 32;
#pragma unroll
    for (int i = 0; i < 4; i++)
        ar[i] = *(const float4*)&A[(size_t)(m0 + am + 32 * i) * K + ak];
#pragma unroll
    for (int i = 0; i < 4; i++)
        br[i] = *(const float4*)&B[(size_t)(bk + 8 * i) * N + n0 + bn];

    for (int kt = 0; kt < nkt; kt++) {
        __syncthreads();
#pragma unroll
        for (int i = 0; i < 4; i++) {
            uint4 u = make_uint4(f2tf(ar[i].x), f2tf(ar[i].y),
                                 f2tf(ar[i].z), f2tf(ar[i].w));
            *(uint4*)&As[(am + 32 * i) * ASTR + ak] = u;
        }
#pragma unroll
        for (int i = 0; i < 4; i++) {
            uint4 u = make_uint4(f2tf(br[i].x), f2tf(br[i].y),
                                 f2tf(br[i].z), f2tf(br[i].w));
            *(uint4*)&Bs[(bk + 8 * i) * BSTR + bn] = u;
        }
        __syncthreads();
        if (kt + 1 < nkt) {
            int kof = (kt + 1) * 32;
#pragma unroll
            for (int i = 0; i < 4; i++)
                ar[i] = *(const float4*)&A[(size_t)(m0 + am + 32 * i) * K + kof + ak];
#pragma unroll
            for (int i = 0; i < 4; i++)
                br[i] = *(const float4*)&B[(size_t)(kof + bk + 8 * i) * N + n0 + bn];
        }
#pragma unroll
        for (int ks = 0; ks < 4; ks++) {
            unsigned a[4][4], b[4][2];
#pragma unroll
            for (int mt = 0; mt < 4; mt++) {
                int mr = wm + mt * 16 + g;
                a[mt][0] = As[mr * ASTR + ks * 8 + t];
                a[mt][1] = As[(mr + 8) * ASTR + ks * 8 + t];
                a[mt][2] = As[mr * ASTR + ks * 8 + t + 4];
                a[mt][3] = As[(mr + 8) * ASTR + ks * 8 + t + 4];
            }
#pragma unroll
            for (int nt = 0; nt < 4; nt++) {
                b[nt][0] = Bs[(ks * 8 + t) * BSTR + wn + nt * 8 + g];
                b[nt][1] = Bs[(ks * 8 + t + 4) * BSTR + wn + nt * 8 + g];
            }
#pragma unroll
            for (int mt = 0; mt < 4; mt++)
#pragma unroll
                for (int nt = 0; nt < 4; nt++)
                    mma8(acc[mt][nt], a[mt][0], a[mt][1], a[mt][2], a[mt][3],
                         b[nt][0], b[nt][1]);
        }
    }
#pragma unroll
    for (int mt = 0; mt < 4; mt++)
#pragma unroll
        for (int nt = 0; nt < 4; nt++) {
            int row = m0 + wm + mt * 16 + g;
            int col = n0 + wn + nt * 8 + 2 * t;
            float2 v0 = make_float2(acc[mt][nt][0], acc[mt][nt][1]);
            float2 v1 = make_float2(acc[mt][nt][2], acc[mt][nt][3]);
            *(float2*)&C[(size_t)row * N + col] = v0;
            *(float2*)&C[(size_t)(row + 8) * N + col] = v1;
        }
}

// ---------------- per-head RMSNorm + RoPE (one warp per (token, head)) -----
__global__ void normrope(const int* __restrict__ pos,
                         const float* __restrict__ qw,
                         const float* __restrict__ kw) {
    int gw = (blockIdx.x * blockDim.x + threadIdx.x) >> 5;
    int lane = threadIdx.x & 31;
    if (gw >= TT * (NH + NKV)) return;
    int t = gw / (NH + NKV);
    int hh = gw - t * (NH + NKV);

    const float* src;
    float* dst;
    const float* w;
    if (hh < NH) {
        src = g_qkv + (size_t)t * QKVN + hh * HD;
        dst = g_q + (size_t)t * QS + hh * HD;
        w = qw;
    } else {
        int kk = hh - NH;
        src = g_qkv + (size_t)t * QKVN + QS + kk * HD;
        dst = g_k + (size_t)t * KVS + kk * HD;
        w = kw;
    }
    float v0 = src[lane], v1 = src[lane + 32], v2 = src[lane + 64], v3 = src[lane + 96];
    float ss = v0 * v0 + v1 * v1 + v2 * v2 + v3 * v3;
#pragma unroll
    for (int o = 16; o; o >>= 1) ss += __shfl_xor_sync(0xffffffffu, ss, o);
    float inv = rsqrtf(ss * (1.0f / 128.0f) + 1e-6f);
    v0 *= inv * w[lane];
    v1 *= inv * w[lane + 32];
    v2 *= inv * w[lane + 64];
    v3 *= inv * w[lane + 96];

    float p = (float)pos[t];
    const float LOG2_THETA = 19.931568569324174f;
    float if0 = exp2f(-LOG2_THETA * (2.0f * lane) * (1.0f / 128.0f));
    float if1 = exp2f(-LOG2_THETA * (2.0f * (lane + 32)) * (1.0f / 128.0f));
    float s0, c0, s1, c1;
    sincosf(p * if0, &s0, &c0);
    sincosf(p * if1, &s1, &c1);
    dst[lane]      = v0 * c0 - v2 * s0;
    dst[lane + 64] = v2 * c0 + v0 * s0;
    dst[lane + 32] = v1 * c1 - v3 * s1;
    dst[lane + 96] = v3 * c1 + v1 * s1;
}

// ---------------- TF32 tensor-core causal GQA flash attention --------------
// BM=128 q-rows, BN=64 kv, 256 threads (8 warps, warp = 16 rows x 64 cols).
#define QSTR 132   // bank = (4m + d) % 32 conflict-free for A-frag loads
#define KSTR 132   // bank = (4n + d) % 32 conflict-free for B-frag loads
#define SSTR 68    // bank = (4m + k) % 32 conflict-free for P A-frag loads
#define FL_SMEM_U32 (128 * QSTR + 64 * KSTR + 64 * KSTR + 128 * SSTR)
#define FL_SMEM_BYTES (FL_SMEM_U32 * 4)

__global__ __launch_bounds__(256, 1)
void flash_tc(const float* __restrict__ gq, const float* __restrict__ gk,
              const float* __restrict__ gv) {
    extern __shared__ unsigned sm[];
    unsigned* Qs = sm;
    unsigned* Ks = Qs + 128 * QSTR;
    unsigned* Vs = Ks + 64 * KSTR;
    unsigned* Ps = Vs + 64 * KSTR;

    int tid = threadIdx.x, w = tid >> 5, lane = tid & 31;
    int g = lane >> 2, t = lane & 3;
    int qt = gridDim.x - 1 - blockIdx.x;   // heavy tiles first
    int h = blockIdx.y, kvh = h >> 1;
    int q0 = qt * 128;
    const float scale = 0.08838834764831845f;

    // load Q tile (pre-scaled, tf32)
    for (int idx = tid; idx < 128 * 32; idx += 256) {
        int r = idx >> 5, dq = (idx & 31) * 4;
        float4 v = *(const float4*)&gq[(size_t)(q0 + r) * QS + h * HD + dq];
        uint4 u = make_uint4(f2tf(v.x * scale), f2tf(v.y * scale),
                             f2tf(v.z * scale), f2tf(v.w * scale));
        *(uint4*)&Qs[r * QSTR + dq] = u;
    }

    float m_[2] = {-INFINITY, -INFINITY};
    float l_[2] = {0.f, 0.f};
    float O[16][4];
#pragma unroll
    for (int dt = 0; dt < 16; dt++)
#pragma unroll
        for (int r = 0; r < 4; r++) O[dt][r] = 0.f;

    int mrow = w * 16 + g;
    int ktmax = 2 * qt + 1;

    for (int kt = 0; kt <= ktmax; kt++) {
        int k0 = kt * 64;
        __syncthreads();
        // load K, V tiles (tf32)
        for (int idx = tid; idx < 64 * 32; idx += 256) {
            int r = idx >> 5, dq = (idx & 31) * 4;
            float4 kv4 = *(const float4*)&gk[(size_t)(k0 + r) * KVS + kvh * HD + dq];
            *(uint4*)&Ks[r * KSTR + dq] =
                make_uint4(f2tf(kv4.x), f2tf(kv4.y), f2tf(kv4.z), f2tf(kv4.w));
            float4 vv = *(const float4*)&gv[(size_t)(k0 + r) * QKVN + kvh * HD + dq];
            *(uint4*)&Vs[r * KSTR + dq] =
                make_uint4(f2tf(vv.x), f2tf(vv.y), f2tf(vv.z), f2tf(vv.w));
        }
        __syncthreads();

        // S = Q K^T  (128 mma per warp)
        float s[8][4];
#pragma unroll
        for (int nt = 0; nt < 8; nt++)
#pragma unroll
            for (int r = 0; r < 4; r++) s[nt][r] = 0.f;
#pragma unroll
        for (int ks = 0; ks < 16; ks++) {
            unsigned a0 = Qs[mrow * QSTR + ks * 8 + t];
            unsigned a1 = Qs[(mrow + 8) * QSTR + ks * 8 + t];
            unsigned a2 = Qs[mrow * QSTR + ks * 8 + t + 4];
            unsigned a3 = Qs[(mrow + 8) * QSTR + ks * 8 + t + 4];
#pragma unroll
            for (int nt = 0; nt < 8; nt++) {
                unsigned b0 = Ks[(nt * 8 + g) * KSTR + ks * 8 + t];
                unsigned b1 = Ks[(nt * 8 + g) * KSTR + ks * 8 + t + 4];
                mma8(s[nt], a0, a1, a2, a3, b0, b1);
            }
        }

        // causal mask (only diagonal-region tiles)
        if (k0 + 63 > q0 + w * 16) {
            int row0 = q0 + w * 16 + g, row1 = row0 + 8;
#pragma unroll
            for (int nt = 0; nt < 8; nt++) {
                int c0 = k0 + nt * 8 + 2 * t, c1 = c0 + 1;
                if (c0 > row0) s[nt][0] = -1e30f;
                if (c1 > row0) s[nt][1] = -1e30f;
                if (c0 > row1) s[nt][2] = -1e30f;
                if (c1 > row1) s[nt][3] = -1e30f;
            }
        }

        // online softmax (rows g, g+8 per thread; quad-consistent)
        float mx0 = -INFINITY, mx1 = -INFINITY;
#pragma unroll
        for (int nt = 0; nt < 8; nt++) {
            mx0 = fmaxf(mx0, fmaxf(s[nt][0], s[nt][1]));
            mx1 = fmaxf(mx1, fmaxf(s[nt][2], s[nt][3]));
        }
        mx0 = fmaxf(mx0, __shfl_xor_sync(0xffffffffu, mx0, 1));
        mx0 = fmaxf(mx0, __shfl_xor_sync(0xffffffffu, mx0, 2));
        mx1 = fmaxf(mx1, __shfl_xor_sync(0xffffffffu, mx1, 1));
        mx1 = fmaxf(mx1, __shfl_xor_sync(0xffffffffu, mx1, 2));
        float mn0 = fmaxf(m_[0], mx0), mn1 = fmaxf(m_[1], mx1);
        float al0 = __expf(m_[0] - mn0), al1 = __expf(m_[1] - mn1);
        m_[0] = mn0; m_[1] = mn1;
        float sum0 = 0.f, sum1 = 0.f;
#pragma unroll
        for (int nt = 0; nt < 8; nt++) {
            float p0 = __expf(s[nt][0] - mn0);
            float p1 = __expf(s[nt][1] - mn0);
            float p2 = __expf(s[nt][2] - mn1);
            float p3 = __expf(s[nt][3] - mn1);
            sum0 += p0 + p1;
            sum1 += p2 + p3;
            int col = nt * 8 + 2 * t;
            Ps[mrow * SSTR + col] = f2tf(p0);
            Ps[mrow * SSTR + col + 1] = f2tf(p1);
            Ps[(mrow + 8) * SSTR + col] = f2tf(p2);
            Ps[(mrow + 8) * SSTR + col + 1] = f2tf(p3);
        }
        sum0 += __shfl_xor_sync(0xffffffffu, sum0, 1);
        sum0 += __shfl_xor_sync(0xffffffffu, sum0, 2);
        sum1 += __shfl_xor_sync(0xffffffffu, sum1, 1);
        sum1 += __shfl_xor_sync(0xffffffffu, sum1, 2);
        l_[0] = al0 * l_[0] + sum0;
        l_[1] = al1 * l_[1] + sum1;
#pragma unroll
        for (int dt = 0; dt < 16; dt++) {
            O[dt][0] *= al0; O[dt][1] *= al0;
            O[dt][2] *= al1; O[dt][3] *= al1;
        }
        __syncwarp();

        // O += P V  (128 mma per warp)
#pragma unroll
        for (int ks = 0; ks < 8; ks++) {
            unsigned a0 = Ps[mrow * SSTR + ks * 8 + t];
            unsigned a1 = Ps[(mrow + 8) * SSTR + ks * 8 + t];
            unsigned a2 = Ps[mrow * SSTR + ks * 8 + t + 4];
            unsigned a3 = Ps[(mrow + 8) * SSTR + ks * 8 + t + 4];
#pragma unroll
            for (int dt = 0; dt < 16; dt++) {
                unsigned b0 = Vs[(ks * 8 + t) * KSTR + dt * 8 + g];
                unsigned b1 = Vs[(ks * 8 + t + 4) * KSTR + dt * 8 + g];
                mma8(O[dt], a0, a1, a2, a3, b0, b1);
            }
        }
    }

    // epilogue
    float i0 = 1.f / l_[0], i1 = 1.f / l_[1];
    int row0 = q0 + w * 16 + g;
#pragma unroll
    for (int dt = 0; dt < 16; dt++) {
        int col = h * HD + dt * 8 + 2 * t;
        *(float2*)&g_att[(size_t)row0 * QS + col] =
            make_float2(O[dt][0] * i0, O[dt][1] * i0);
        *(float2*)&g_att[(size_t)(row0 + 8) * QS + col] =
            make_float2(O[dt][2] * i1, O[dt][3] * i1);
    }
}

// ---------------------------------------------------------------------------
extern "C" void kernel_launch(void* const* d_in, const int* in_sizes, int n_in,
                              void* d_out, int out_size) {
    const int* positions = (const int*)d_in[0];
    const float* hs = (const float*)d_in[1];
    const float* w_qkv = (const float*)d_in[2];
    const float* w_o = (const float*)d_in[3];
    const float* qw = (const float*)d_in[4];
    const float* kw = (const float*)d_in[5];
    float* out = (float*)d_out;

    float* p_qkv = nullptr;
    float* p_q = nullptr;
    float* p_k = nullptr;
    float* p_att = nullptr;
    cudaGetSymbolAddress((void**)&p_qkv, g_qkv);
    cudaGetSymbolAddress((void**)&p_q, g_q);
    cudaGetSymbolAddress((void**)&p_k, g_k);
    cudaGetSymbolAddress((void**)&p_att, g_att);
    cudaFuncSetAttribute(flash_tc,
                         cudaFuncAttributeMaxDynamicSharedMemorySize, FL_SMEM_BYTES);

    // 1) QKV projection
    gemm_tc<<<dim3(QKVN / 128, TT / 128), 256>>>(hs, w_qkv, p_qkv, TT, QKVN, HH);
    // 2) per-head RMSNorm + RoPE
    normrope<<<(TT * (NH + NKV)) / 8, 256>>>(positions, qw, kw);
    // 3) causal GQA flash attention (tensor cores)
    flash_tc<<<dim3(TT / 128, NH), 256, FL_SMEM_BYTES>>>(p_q, p_k, p_qkv + QS + KVS);
    // 4) output projection
    gemm_tc<<<dim3(HH / 128, TT / 128), 256>>>(p_att, w_o, out, TT, HH, QS);
}